// round 16
// baseline (speedup 1.0000x reference)
#include <cuda_runtime.h>
#include <math.h>

#define NB 8
#define C1 128
#define HH 128
#define WW 128
#define HW (HH*WW)
#define KK 7
#define SS 4
#define DD 49
#define D8 56
#define NPH 31
#define PP 19
#define NPATCH (PP*PP)
#define NT 448
#define WTS 132
#define EXQ 7296

__device__ __forceinline__ int crow(int c) { return c*D8 + (c & ~3); }

// ---------------- scratch (static device globals) ----------------
__device__ float g_exsum[NB*C1*HW];
__device__ float g_qsum [NB*C1*HW];
__device__ float g_dwex [NB*C1*HW];
__device__ float g_dwq  [NB*C1*HW];
__device__ float g_cat  [NB*2*C1*HW];
__device__ float g_dwf  [NB*2*C1*HW];

#define S_EX    0
#define S_Q     (EXQ)
#define S_COR   (2*EXQ)
#define S_B     (3*EXQ)
#define S_A1    (S_B  + D8*D8)
#define S_CMAX  (S_A1 + D8*D8)
#define S_CRS   (S_CMAX + D8)
#define S_RMAX  (S_CRS  + D8)
#define S_RRS   (S_RMAX + D8)
#define S_ME    (S_RRS  + D8)
#define S_MQ    (S_ME   + D8)
#define S_G1    (S_MQ   + D8)
#define S_G2    (S_G1   + C1)
#define S_TOT   (S_G2   + C1)
#define SMEM_BYTES (S_TOT * 4)       // 115,008 B -> 2 CTAs/SM

__device__ __forceinline__ int pmap(int t) { return (t / 7) * 8 + (t % 7); }

__global__ void noop_kernel() {}   // keeps ncu capture slot on attn

// =====================================================================
__global__ __launch_bounds__(NT, 2) void attn_kernel(
    const float* __restrict__ ex, const float* __restrict__ q,
    const float* __restrict__ wce, const float* __restrict__ g1,
    const float* __restrict__ g2)
{
    extern __shared__ float sm[];
    float* s_ex  = sm + S_EX;
    float* s_q   = sm + S_Q;
    float* s_cor = sm + S_COR;
    float* s_b   = sm + S_B;
    float* s_a1  = sm + S_A1;
    float* s_wt  = sm + S_B;
    float* s_cmax= sm + S_CMAX;
    float* s_crs = sm + S_CRS;
    float* s_rmax= sm + S_RMAX;
    float* s_rrs = sm + S_RRS;
    float* s_me  = sm + S_ME;
    float* s_mq  = sm + S_MQ;
    float* s_g1  = sm + S_G1;
    float* s_g2  = sm + S_G2;

    const int tid  = threadIdx.x;
    const int lane = tid & 31;
    const int wid  = tid >> 5;
    const int n    = blockIdx.x / NPATCH;
    const int pv   = blockIdx.x % NPATCH;
    const int phv  = pv / PP, pwv = pv % PP;
    const int b    = phv * NPH + pwv;

    const bool act  = tid < 224;
    const int  c0w  = (tid / 14) * 8;
    const int  t14  = (tid % 14) * 4;
    const int  cb0  = crow(c0w);
    const int  cb1  = cb0 + 4*D8 + 4;

    if (tid < C1) { s_g1[tid] = g1[tid]; s_g2[tid] = g2[tid]; }

    // ---- vectorized patch load, coalesced mapping ----
    const float* exn = ex + (size_t)n*C1*HW;
    const float* qn  = q  + (size_t)n*C1*HW;
    #pragma unroll
    for (int it = 0; it < 2; it++) {
        int task = tid + it*NT;
        if (task < C1*KK) {
            int kh = task / C1, cp = task % C1;
            int m  = b*C1 + cp;
            int c  = m / 961;
            int p  = m % 961;
            int pht = p / NPH, pwt = p % NPH;
            int base = c*HW + (pht*SS + kh)*WW + pwt*SS;
            int r = crow(cp) + kh*8;
            float4 v0 = *(const float4*)(exn + base);
            float4 v1 = *(const float4*)(exn + base + 4);
            v1.w = 0.f;
            *(float4*)&s_ex[r]     = v0;
            *(float4*)&s_ex[r + 4] = v1;
            float4 u0 = *(const float4*)(qn + base);
            float4 u1 = *(const float4*)(qn + base + 4);
            u1.w = 0.f;
            *(float4*)&s_q[r]     = u0;
            *(float4*)&s_q[r + 4] = u1;
        }
    }

    // ---- stage 1: corr[c][d] = sum_k w[c][k]*ex[k][d]; 8c x 4d tiles ----
    {
        float acc[8][4] = {};
        for (int ch = 0; ch < 4; ch++) {
            __syncthreads();
            for (int t2 = tid; t2 < 1024; t2 += NT) {
                int c = t2 >> 3, kq = (t2 & 7) * 4;
                float4 wv = __ldg((const float4*)(wce + (size_t)c*C1 + ch*32 + kq));
                s_wt[(kq+0)*WTS + c] = wv.x;
                s_wt[(kq+1)*WTS + c] = wv.y;
                s_wt[(kq+2)*WTS + c] = wv.z;
                s_wt[(kq+3)*WTS + c] = wv.w;
            }
            __syncthreads();
            if (act) {
                #pragma unroll 2
                for (int k4 = 0; k4 < 32; k4 += 4) {
                    int kb = crow(ch*32 + k4);
                    #pragma unroll
                    for (int j = 0; j < 4; j++) {
                        float4 ev = *(const float4*)&s_ex[kb + j*D8 + t14];
                        float4 wl = *(const float4*)&s_wt[(k4+j)*WTS + c0w];
                        float4 wh = *(const float4*)&s_wt[(k4+j)*WTS + c0w + 4];
                        acc[0][0]+=wl.x*ev.x; acc[0][1]+=wl.x*ev.y; acc[0][2]+=wl.x*ev.z; acc[0][3]+=wl.x*ev.w;
                        acc[1][0]+=wl.y*ev.x; acc[1][1]+=wl.y*ev.y; acc[1][2]+=wl.y*ev.z; acc[1][3]+=wl.y*ev.w;
                        acc[2][0]+=wl.z*ev.x; acc[2][1]+=wl.z*ev.y; acc[2][2]+=wl.z*ev.z; acc[2][3]+=wl.z*ev.w;
                        acc[3][0]+=wl.w*ev.x; acc[3][1]+=wl.w*ev.y; acc[3][2]+=wl.w*ev.z; acc[3][3]+=wl.w*ev.w;
                        acc[4][0]+=wh.x*ev.x; acc[4][1]+=wh.x*ev.y; acc[4][2]+=wh.x*ev.z; acc[4][3]+=wh.x*ev.w;
                        acc[5][0]+=wh.y*ev.x; acc[5][1]+=wh.y*ev.y; acc[5][2]+=wh.y*ev.z; acc[5][3]+=wh.y*ev.w;
                        acc[6][0]+=wh.z*ev.x; acc[6][1]+=wh.z*ev.y; acc[6][2]+=wh.z*ev.z; acc[6][3]+=wh.z*ev.w;
                        acc[7][0]+=wh.w*ev.x; acc[7][1]+=wh.w*ev.y; acc[7][2]+=wh.w*ev.z; acc[7][3]+=wh.w*ev.w;
                    }
                }
            }
        }
        __syncthreads();
        if (act) {
            #pragma unroll
            for (int i = 0; i < 4; i++) {
                *(float4*)&s_cor[cb0 + i*D8 + t14] = make_float4(acc[i  ][0],acc[i  ][1],acc[i  ][2],acc[i  ][3]);
                *(float4*)&s_cor[cb1 + i*D8 + t14] = make_float4(acc[i+4][0],acc[i+4][1],acc[i+4][2],acc[i+4][3]);
            }
        }
    }
    __syncthreads();

    // ---- stage 2: A[d][e] = sum_c corr[c][d]*q[c][e]; 8d x 4e, split-K x2 ----
    if (tid < 196) {
        const int th = tid % 98;
        const int ks = tid / 98;
        const int d0 = (th / 14) * 8;
        const int e0 = (th % 14) * 4;
        const int k0 = ks * 64;
        float acc[8][4] = {};
        for (int c4 = k0; c4 < k0 + 64; c4 += 4) {
            int cr = crow(c4);
            #pragma unroll
            for (int j = 0; j < 4; j++) {
                const float* rp = &s_cor[cr + j*D8];
                float4 cl = *(const float4*)(rp + d0);
                float4 ch = *(const float4*)(rp + d0 + 4);
                float4 qe = *(const float4*)&s_q[cr + j*D8 + e0];
                acc[0][0]+=cl.x*qe.x; acc[0][1]+=cl.x*qe.y; acc[0][2]+=cl.x*qe.z; acc[0][3]+=cl.x*qe.w;
                acc[1][0]+=cl.y*qe.x; acc[1][1]+=cl.y*qe.y; acc[1][2]+=cl.y*qe.z; acc[1][3]+=cl.y*qe.w;
                acc[2][0]+=cl.z*qe.x; acc[2][1]+=cl.z*qe.y; acc[2][2]+=cl.z*qe.z; acc[2][3]+=cl.z*qe.w;
                acc[3][0]+=cl.w*qe.x; acc[3][1]+=cl.w*qe.y; acc[3][2]+=cl.w*qe.z; acc[3][3]+=cl.w*qe.w;
                acc[4][0]+=ch.x*qe.x; acc[4][1]+=ch.x*qe.y; acc[4][2]+=ch.x*qe.z; acc[4][3]+=ch.x*qe.w;
                acc[5][0]+=ch.y*qe.x; acc[5][1]+=ch.y*qe.y; acc[5][2]+=ch.y*qe.z; acc[5][3]+=ch.y*qe.w;
                acc[6][0]+=ch.z*qe.x; acc[6][1]+=ch.z*qe.y; acc[6][2]+=ch.z*qe.z; acc[6][3]+=ch.z*qe.w;
                acc[7][0]+=ch.w*qe.x; acc[7][1]+=ch.w*qe.y; acc[7][2]+=ch.w*qe.z; acc[7][3]+=ch.w*qe.w;
            }
        }
        float* dst = ks ? s_a1 : s_b;
        #pragma unroll
        for (int i = 0; i < 8; i++)
            *(float4*)&dst[(d0+i)*D8 + e0] = make_float4(acc[i][0],acc[i][1],acc[i][2],acc[i][3]);
    }
    __syncthreads();

    // ---- col-softmax stats ----
    {
        float* spm = s_cor;
        float* sps = s_cor + 896;
        float m0=-1e30f, s0=0.f, m1=-1e30f, s1=0.f;
        const int c0p = pmap(lane);
        const int c1p = (lane < 17) ? pmap(lane + 32) : 0;
        for (int dt = wid; dt < DD; dt += 14) {
            int dp = pmap(dt);
            float v = s_b[dp*D8 + c0p] + s_a1[dp*D8 + c0p];
            if (v > m0) { s0 = s0*__expf(m0 - v) + 1.f; m0 = v; } else s0 += __expf(v - m0);
            if (lane < 17) {
                float u = s_b[dp*D8 + c1p] + s_a1[dp*D8 + c1p];
                if (u > m1) { s1 = s1*__expf(m1 - u) + 1.f; m1 = u; } else s1 += __expf(u - m1);
            }
        }
        spm[wid*52 + lane] = m0;
        sps[wid*52 + lane] = s0;
        if (lane < 17) { spm[wid*52 + 32 + lane] = m1; sps[wid*52 + 32 + lane] = s1; }
    }
    // ---- row-softmax stats ----
    for (int task = wid; task < DD; task += 14) {
        int dp = pmap(task);
        int ep0 = pmap(lane);
        float v0 = s_b[dp*D8 + ep0] + s_a1[dp*D8 + ep0];
        float v1 = -1e30f;
        if (lane < 17) { int ep1 = pmap(lane + 32); v1 = s_b[dp*D8 + ep1] + s_a1[dp*D8 + ep1]; }
        float m = fmaxf(v0, v1);
        #pragma unroll
        for (int o = 16; o; o >>= 1) m = fmaxf(m, __shfl_xor_sync(~0u, m, o));
        float s = __expf(v0 - m) + ((lane < 17) ? __expf(v1 - m) : 0.f);
        #pragma unroll
        for (int o = 16; o; o >>= 1) s += __shfl_xor_sync(~0u, s, o);
        if (lane == 0) { s_rmax[dp] = m; s_rrs[dp] = 1.f / s; }
    }
    __syncthreads();
    if (tid < DD) {
        float* spm = s_cor;
        float* sps = s_cor + 896;
        float m = -1e30f;
        #pragma unroll
        for (int w2 = 0; w2 < 14; w2++) m = fmaxf(m, spm[w2*52 + tid]);
        float s = 0.f;
        #pragma unroll
        for (int w2 = 0; w2 < 14; w2++) s += sps[w2*52 + tid] * __expf(spm[w2*52 + tid] - m);
        s_cmax[pmap(tid)] = m;
        s_crs [pmap(tid)] = 1.f / s;
    }
    __syncthreads();

    // ---- softmax exp pass ----
    for (int i = tid; i < D8*D8; i += NT) {
        int dp = i / D8, ep = i % D8;
        bool pad = ((dp & 7) == 7) || ((ep & 7) == 7);
        float a = s_b[i] + s_a1[i];
        float a1v = pad ? 0.f : __expf(a - s_cmax[ep]) * s_crs[ep];
        float b2v = pad ? 0.f : __expf(a - s_rmax[dp]) * s_rrs[dp];
        s_a1[i] = a1v;
        s_b [i] = b2v;
    }
    __syncthreads();

    // ---- stage 3a: query_att[c][e] = sum_d ex[c][d]*A1[d][e]; 8c x 4e ----
    {
        float acc[8][4] = {};
        if (act) {
            for (int d4 = 0; d4 < D8; d4 += 4) {
                float4 a0v = *(const float4*)&s_a1[(d4+0)*D8 + t14];
                float4 a1v = *(const float4*)&s_a1[(d4+1)*D8 + t14];
                float4 a2v = *(const float4*)&s_a1[(d4+2)*D8 + t14];
                float4 a3v = *(const float4*)&s_a1[(d4+3)*D8 + t14];
                #pragma unroll
                for (int h = 0; h < 2; h++) {
                    int cb = h ? cb1 : cb0;
                    int o  = h * 4;
                    float4 x0 = *(const float4*)&s_ex[cb + 0*D8 + d4];
                    float4 x1 = *(const float4*)&s_ex[cb + 1*D8 + d4];
                    float4 x2 = *(const float4*)&s_ex[cb + 2*D8 + d4];
                    float4 x3 = *(const float4*)&s_ex[cb + 3*D8 + d4];
                    acc[o+0][0]+=x0.x*a0v.x+x0.y*a1v.x+x0.z*a2v.x+x0.w*a3v.x;
                    acc[o+0][1]+=x0.x*a0v.y+x0.y*a1v.y+x0.z*a2v.y+x0.w*a3v.y;
                    acc[o+0][2]+=x0.x*a0v.z+x0.y*a1v.z+x0.z*a2v.z+x0.w*a3v.z;
                    acc[o+0][3]+=x0.x*a0v.w+x0.y*a1v.w+x0.z*a2v.w+x0.w*a3v.w;
                    acc[o+1][0]+=x1.x*a0v.x+x1.y*a1v.x+x1.z*a2v.x+x1.w*a3v.x;
                    acc[o+1][1]+=x1.x*a0v.y+x1.y*a1v.y+x1.z*a2v.y+x1.w*a3v.y;
                    acc[o+1][2]+=x1.x*a0v.z+x1.y*a1v.z+x1.z*a2v.z+x1.w*a3v.z;
                    acc[o+1][3]+=x1.x*a0v.w+x1.y*a1v.w+x1.z*a2v.w+x1.w*a3v.w;
                    acc[o+2][0]+=x2.x*a0v.x+x2.y*a1v.x+x2.z*a2v.x+x2.w*a3v.x;
                    acc[o+2][1]+=x2.x*a0v.y+x2.y*a1v.y+x2.z*a2v.y+x2.w*a3v.y;
                    acc[o+2][2]+=x2.x*a0v.z+x2.y*a1v.z+x2.z*a2v.z+x2.w*a3v.z;
                    acc[o+2][3]+=x2.x*a0v.w+x2.y*a1v.w+x2.z*a2v.w+x2.w*a3v.w;
                    acc[o+3][0]+=x3.x*a0v.x+x3.y*a1v.x+x3.z*a2v.x+x3.w*a3v.x;
                    acc[o+3][1]+=x3.x*a0v.y+x3.y*a1v.y+x3.z*a2v.y+x3.w*a3v.y;
                    acc[o+3][2]+=x3.x*a0v.z+x3.y*a1v.z+x3.z*a2v.z+x3.w*a3v.z;
                    acc[o+3][3]+=x3.x*a0v.w+x3.y*a1v.w+x3.z*a2v.w+x3.w*a3v.w;
                }
            }
        }
        __syncthreads();
        if (act) {
            #pragma unroll
            for (int i = 0; i < 4; i++) {
                *(float4*)&s_cor[cb0 + i*D8 + t14] = make_float4(acc[i  ][0],acc[i  ][1],acc[i  ][2],acc[i  ][3]);
                *(float4*)&s_cor[cb1 + i*D8 + t14] = make_float4(acc[i+4][0],acc[i+4][1],acc[i+4][2],acc[i+4][3]);
            }
        }
    }
    __syncthreads();

    // ---- stage 3b: exemplar_att[c][d] = sum_e q[c][e]*B2[d][e]; 8c x 4d ----
    {
        float acc[8][4] = {};
        if (act) {
            for (int e4 = 0; e4 < D8; e4 += 4) {
                float4 b0 = *(const float4*)&s_b[(t14+0)*D8 + e4];
                float4 b1 = *(const float4*)&s_b[(t14+1)*D8 + e4];
                float4 b2 = *(const float4*)&s_b[(t14+2)*D8 + e4];
                float4 b3 = *(const float4*)&s_b[(t14+3)*D8 + e4];
                #pragma unroll
                for (int h = 0; h < 2; h++) {
                    int cb = h ? cb1 : cb0;
                    int o  = h * 4;
                    float4 q0 = *(const float4*)&s_q[cb + 0*D8 + e4];
                    float4 q1 = *(const float4*)&s_q[cb + 1*D8 + e4];
                    float4 q2 = *(const float4*)&s_q[cb + 2*D8 + e4];
                    float4 q3 = *(const float4*)&s_q[cb + 3*D8 + e4];
                    acc[o+0][0]+=q0.x*b0.x+q0.y*b0.y+q0.z*b0.z+q0.w*b0.w;
                    acc[o+0][1]+=q0.x*b1.x+q0.y*b1.y+q0.z*b1.z+q0.w*b1.w;
                    acc[o+0][2]+=q0.x*b2.x+q0.y*b2.y+q0.z*b2.z+q0.w*b2.w;
                    acc[o+0][3]+=q0.x*b3.x+q0.y*b3.y+q0.z*b3.z+q0.w*b3.w;
                    acc[o+1][0]+=q1.x*b0.x+q1.y*b0.y+q1.z*b0.z+q1.w*b0.w;
                    acc[o+1][1]+=q1.x*b1.x+q1.y*b1.y+q1.z*b1.z+q1.w*b1.w;
                    acc[o+1][2]+=q1.x*b2.x+q1.y*b2.y+q1.z*b2.z+q1.w*b2.w;
                    acc[o+1][3]+=q1.x*b3.x+q1.y*b3.y+q1.z*b3.z+q1.w*b3.w;
                    acc[o+2][0]+=q2.x*b0.x+q2.y*b0.y+q2.z*b0.z+q2.w*b0.w;
                    acc[o+2][1]+=q2.x*b1.x+q2.y*b1.y+q2.z*b1.z+q2.w*b1.w;
                    acc[o+2][2]+=q2.x*b2.x+q2.y*b2.y+q2.z*b2.z+q2.w*b2.w;
                    acc[o+2][3]+=q2.x*b3.x+q2.y*b3.y+q2.z*b3.z+q2.w*b3.w;
                    acc[o+3][0]+=q3.x*b0.x+q3.y*b0.y+q3.z*b0.z+q3.w*b0.w;
                    acc[o+3][1]+=q3.x*b1.x+q3.y*b1.y+q3.z*b1.z+q3.w*b1.w;
                    acc[o+3][2]+=q3.x*b2.x+q3.y*b2.y+q3.z*b2.z+q3.w*b2.w;
                    acc[o+3][3]+=q3.x*b3.x+q3.y*b3.y+q3.z*b3.z+q3.w*b3.w;
                }
            }
        }
        __syncthreads();
        if (act) {
            #pragma unroll
            for (int i = 0; i < 4; i++) {
                *(float4*)&s_ex[cb0 + i*D8 + t14] = make_float4(acc[i  ][0],acc[i  ][1],acc[i  ][2],acc[i  ][3]);
                *(float4*)&s_ex[cb1 + i*D8 + t14] = make_float4(acc[i+4][0],acc[i+4][1],acc[i+4][2],acc[i+4][3]);
            }
        }
    }
    __syncthreads();

    // ---- gates ----
    {
        float* sp1 = s_a1;
        float* sp2 = s_a1 + 896;
        float p0 = 0.f, p1 = 0.f, r0 = 0.f, r1 = 0.f;
        for (int c = wid; c < C1; c += 14) {
            int cr = crow(c);
            float gA = s_g1[c], gB = s_g2[c];
            p0 += gA * s_ex [cr + lane];
            r0 += gB * s_cor[cr + lane];
            if (lane < 24) {
                p1 += gA * s_ex [cr + 32 + lane];
                r1 += gB * s_cor[cr + 32 + lane];
            }
        }
        sp1[wid*64 + lane] = p0;
        sp2[wid*64 + lane] = r0;
        if (lane < 24) { sp1[wid*64 + 32 + lane] = p1; sp2[wid*64 + 32 + lane] = r1; }
    }
    __syncthreads();
    if (tid < D8) {
        float* sp1 = s_a1;
        float* sp2 = s_a1 + 896;
        float sa = 0.f, sb2 = 0.f;
        #pragma unroll
        for (int w2 = 0; w2 < 14; w2++) { sa += sp1[w2*64 + tid]; sb2 += sp2[w2*64 + tid]; }
        s_me[tid] = 1.f / (1.f + __expf(-sa));
        s_mq[tid] = 1.f / (1.f + __expf(-sb2));
    }
    __syncthreads();

    // ---- recon + residual ----
    for (int i = tid; i < C1*DD; i += NT) {
        int c = i / DD, d = i % DD;
        int kh = d / KK, kw = d % KK;
        int dp = kh*8 + kw;
        int cr = crow(c);
        int y = phv*KK + kh, x = pwv*KK + kw;
        if (y < HH && x < WW) {
            size_t gi = (size_t)(n*C1 + c)*HW + y*WW + x;
            g_exsum[gi] = s_ex [cr + dp]*s_me[dp] + ex[gi];
            g_qsum [gi] = s_cor[cr + dp]*s_mq[dp] + q [gi];
        }
    }
}

// =====================================================================
// Depthwise 3x3 + BN + ReLU — 1 thread = 8 pixels, dual-stream.
// =====================================================================
__global__ __launch_bounds__(256) void dw8_kernel(
    const float* __restrict__ in0, const float* __restrict__ in1,
    float* __restrict__ out0, float* __restrict__ out1,
    const float* __restrict__ w, const float* __restrict__ g,
    const float* __restrict__ b, int Ctot, int total8)
{
    int idx = blockIdx.x*blockDim.x + threadIdx.x;
    if (idx >= total8) return;
    const float* in  = blockIdx.y ? in1  : in0;
    float*       out = blockIdx.y ? out1 : out0;
    const int W8 = WW / 8;
    int x8    = (idx % W8) * 8;
    int y     = (idx / W8) % HH;
    int plane = idx / (W8 * HH);
    int c     = plane % Ctot;
    const float* ip = in + (size_t)plane*HW;

    const float* wc = w + c*9;
    float w00=wc[0], w01=wc[1], w02=wc[2];
    float w10=wc[3], w11=wc[4], w12=wc[5];
    float w20=wc[6], w21=wc[7], w22=wc[8];

    float acc[8] = {};

    #pragma unroll
    for (int dy = -1; dy <= 1; dy++) {
        int yy = y + dy;
        if (yy < 0 || yy >= HH) continue;
        const float* row = ip + yy*WW;
        float4 M0 = *(const float4*)(row + x8);
        float4 M1 = *(const float4*)(row + x8 + 4);
        float lm = (x8 > 0)      ? row[x8 - 1] : 0.f;
        float rp = (x8 + 8 < WW) ? row[x8 + 8] : 0.f;
        float wa = (dy < 0) ? w00 : (dy ? w20 : w10);
        float wb = (dy < 0) ? w01 : (dy ? w21 : w11);
        float wd = (dy < 0) ? w02 : (dy ? w22 : w12);
        float v[10] = {lm, M0.x, M0.y, M0.z, M0.w, M1.x, M1.y, M1.z, M1.w, rp};
        #pragma unroll
        for (int i = 0; i < 8; i++)
            acc[i] += wa*v[i] + wb*v[i+1] + wd*v[i+2];
    }

    float gs = g[c] * rsqrtf(1.f + 1e-5f);
    float bb = b[c];
    float* ob = out + (size_t)plane*HW + y*WW + x8;
    float4 o0, o1;
    o0.x = fmaxf(acc[0]*gs + bb, 0.f);
    o0.y = fmaxf(acc[1]*gs + bb, 0.f);
    o0.z = fmaxf(acc[2]*gs + bb, 0.f);
    o0.w = fmaxf(acc[3]*gs + bb, 0.f);
    o1.x = fmaxf(acc[4]*gs + bb, 0.f);
    o1.y = fmaxf(acc[5]*gs + bb, 0.f);
    o1.z = fmaxf(acc[6]*gs + bb, 0.f);
    o1.w = fmaxf(acc[7]*gs + bb, 0.f);
    *(float4*)(ob)     = o0;
    *(float4*)(ob + 4) = o1;
}

// =====================================================================
// Pointwise 1x1 conv as SGEMM: 128co x 128px tile, 8x8 micro,
// k-chunk 16 (half the barriers), double-buffered smem + reg prefetch.
// =====================================================================
template<int CIN>
__global__ __launch_bounds__(256) void pw_kernel(
    const float* __restrict__ in0, const float* __restrict__ in1,
    float* __restrict__ out,
    const float* __restrict__ w, const float* __restrict__ gsc,
    const float* __restrict__ bsc, int ostride)
{
    __shared__ float As[2][16][128];
    __shared__ float Bs[2][16][128];
    const int n   = blockIdx.z;
    const int px0 = blockIdx.x * 128;
    const int co_off = blockIdx.y * C1;
    const float* in = blockIdx.y ? in1 : in0;
    const int t   = threadIdx.x;
    const int tx  = t % 16, ty = t / 16;
    const int ci  = t % 128, k8 = (t / 128) * 8;
    const int kr  = t / 16,  pc = (t % 16) * 8;

    float acc[8][8] = {};
    const float* inb = in + (size_t)n*CIN*HW + px0;

    float4 wv0 = __ldg((const float4*)(w + (size_t)ci*CIN + k8));
    float4 wv1 = __ldg((const float4*)(w + (size_t)ci*CIN + k8 + 4));
    float4 bv0 = __ldg((const float4*)(inb + (size_t)kr*HW + pc));
    float4 bv1 = __ldg((const float4*)(inb + (size_t)kr*HW + pc + 4));

    for (int kt = 0; kt < CIN; kt += 16) {
        int buf = (kt >> 4) & 1;
        As[buf][k8+0][ci] = wv0.x; As[buf][k8+1][ci] = wv0.y;
        As[buf][k8+2][ci] = wv0.z; As[buf][k8+3][ci] = wv0.w;
        As[buf][k8+4][ci] = wv1.x; As[buf][k8+5][ci] = wv1.y;
        As[buf][k8+6][ci] = wv1.z; As[buf][k8+7][ci] = wv1.w;
        *(float4*)&Bs[buf][kr][pc]     = bv0;
        *(float4*)&Bs[buf][kr][pc + 4] = bv1;
        __syncthreads();
        if (kt + 16 < CIN) {
            wv0 = __ldg((const float4*)(w + (size_t)ci*CIN + kt + 16 + k8));
            wv1 = __ldg((const float4*)(w + (size_t)ci*CIN + kt + 16 + k8 + 4));
            bv0 = __ldg((const float4*)(inb + (size_t)(kt + 16 + kr)*HW + pc));
            bv1 = __ldg((const float4*)(inb + (size_t)(kt + 16 + kr)*HW + pc + 4));
        }
        #pragma unroll
        for (int k = 0; k < 16; k++) {
            float4 a0 = *(float4*)&As[buf][k][ty*4];
            float4 a1 = *(float4*)&As[buf][k][64 + ty*4];
            float4 b0 = *(float4*)&Bs[buf][k][tx*4];
            float4 b1 = *(float4*)&Bs[buf][k][64 + tx*4];
            acc[0][0]+=a0.x*b0.x; acc[0][1]+=a0.x*b0.y; acc[0][2]+=a0.x*b0.z; acc[0][3]+=a0.x*b0.w;
            acc[0][4]+=a0.x*b1.x; acc[0][5]+=a0.x*b1.y; acc[0][6]+=a0.x*b1.z; acc[0][7]+=a0.x*b1.w;
            acc[1][0]+=a0.y*b0.x; acc[1][1]+=a0.y*b0.y; acc[1][2]+=a0.y*b0.z; acc[1][3]+=a0.y*b0.w;
            acc[1][4]+=a0.y*b1.x; acc[1][5]+=a0.y*b1.y; acc[1][6]+=a0.y*b1.z; acc[1][7]+=a0.y*b1.w;
            acc[2][0]+=a0.z*b0.x; acc[2][1]+=a0.z*b0.y; acc[2][2]+=a0.z*b0.z; acc[2][3]+=a0.z*b0.w;
            acc[2][4]+=a0.z*b1.x; acc[2][5]+=a0.z*b1.y; acc[2][6]+=a0.z*b1.z; acc[2][7]+=a0.z*b1.w;
            acc[3][0]+=a0.w*b0.x; acc[3][1]+=a0.w*b0.y; acc[3][2]+=a0.w*b0.z; acc[3][3]+=a0.w*b0.w;
            acc[3][4]+=a0.w*b1.x; acc[3][5]+=a0.w*b1.y; acc[3][6]+=a0.w*b1.z; acc[3][7]+=a0.w*b1.w;
            acc[4][0]+=a1.x*b0.x; acc[4][1]+=a1.x*b0.y; acc[4][2]+=a1.x*b0.z; acc[4][3]+=a1.x*b0.w;
            acc[4][4]+=a1.x*b1.x; acc[4][5]+=a1.x*b1.y; acc[4][6]+=a1.x*b1.z; acc[4][7]+=a1.x*b1.w;
            acc[5][0]+=a1.y*b0.x; acc[5][1]+=a1.y*b0.y; acc[5][2]+=a1.y*b0.z; acc[5][3]+=a1.y*b0.w;
            acc[5][4]+=a1.y*b1.x; acc[5][5]+=a1.y*b1.y; acc[5][6]+=a1.y*b1.z; acc[5][7]+=a1.y*b1.w;
            acc[6][0]+=a1.z*b0.x; acc[6][1]+=a1.z*b0.y; acc[6][2]+=a1.z*b0.z; acc[6][3]+=a1.z*b0.w;
            acc[6][4]+=a1.z*b1.x; acc[6][5]+=a1.z*b1.y; acc[6][6]+=a1.z*b1.z; acc[6][7]+=a1.z*b1.w;
            acc[7][0]+=a1.w*b0.x; acc[7][1]+=a1.w*b0.y; acc[7][2]+=a1.w*b0.z; acc[7][3]+=a1.w*b0.w;
            acc[7][4]+=a1.w*b1.x; acc[7][5]+=a1.w*b1.y; acc[7][6]+=a1.w*b1.z; acc[7][7]+=a1.w*b1.w;
        }
        __syncthreads();
    }

    #pragma unroll
    for (int i = 0; i < 8; i++) {
        int co = (i < 4) ? (ty*4 + i) : (64 + ty*4 + (i - 4));
        float gv = gsc[co] * rsqrtf(1.f + 1e-5f);
        float bb = bsc[co];
        float* ob = out + ((size_t)n*ostride + co_off + co)*HW + px0;
        float4 o0, o1;
        o0.x = fmaxf(acc[i][0]*gv + bb, 0.f);
        o0.y = fmaxf(acc[i][1]*gv + bb, 0.f);
        o0.z = fmaxf(acc[i][2]*gv + bb, 0.f);
        o0.w = fmaxf(acc[i][3]*gv + bb, 0.f);
        o1.x = fmaxf(acc[i][4]*gv + bb, 0.f);
        o1.y = fmaxf(acc[i][5]*gv + bb, 0.f);
        o1.z = fmaxf(acc[i][6]*gv + bb, 0.f);
        o1.w = fmaxf(acc[i][7]*gv + bb, 0.f);
        *(float4*)(ob + tx*4)      = o0;
        *(float4*)(ob + 64 + tx*4) = o1;
    }
}

// =====================================================================
extern "C" void kernel_launch(void* const* d_in, const int* in_sizes, int n_in,
                              void* d_out, int out_size)
{
    const float* exemplar = (const float*)d_in[0];
    const float* query    = (const float*)d_in[1];
    const float* w_conv_e = (const float*)d_in[2];
    const float* w_gate1  = (const float*)d_in[3];
    const float* w_gate2  = (const float*)d_in[4];
    const float* dw1_w    = (const float*)d_in[5];
    const float* bn1a_g   = (const float*)d_in[6];
    const float* bn1a_b   = (const float*)d_in[7];
    const float* pw1_w    = (const float*)d_in[8];
    const float* bn1b_g   = (const float*)d_in[9];
    const float* bn1b_b   = (const float*)d_in[10];
    const float* dwf_w    = (const float*)d_in[11];
    const float* bnfa_g   = (const float*)d_in[12];
    const float* bnfa_b   = (const float*)d_in[13];
    const float* pwf_w    = (const float*)d_in[14];
    const float* bnfb_g   = (const float*)d_in[15];
    const float* bnfb_b   = (const float*)d_in[16];

    float *p_exsum, *p_qsum, *p_dwex, *p_dwq, *p_cat, *p_dwf;
    cudaGetSymbolAddress((void**)&p_exsum, g_exsum);
    cudaGetSymbolAddress((void**)&p_qsum,  g_qsum);
    cudaGetSymbolAddress((void**)&p_dwex,  g_dwex);
    cudaGetSymbolAddress((void**)&p_dwq,   g_dwq);
    cudaGetSymbolAddress((void**)&p_cat,   g_cat);
    cudaGetSymbolAddress((void**)&p_dwf,   g_dwf);

    cudaFuncSetAttribute(attn_kernel, cudaFuncAttributeMaxDynamicSharedMemorySize, SMEM_BYTES);

    // keep ncu capture slot on attn
    noop_kernel<<<1, 32>>>();
    noop_kernel<<<1, 32>>>();
    noop_kernel<<<1, 32>>>();

    attn_kernel<<<NB*NPATCH, NT, SMEM_BYTES>>>(exemplar, query, w_conv_e, w_gate1, w_gate2);

    int tot1_8 = NB*C1*HW/8;
    dw8_kernel<<<dim3(tot1_8/256, 2), 256>>>(p_exsum, p_qsum, p_dwex, p_dwq,
                                             dw1_w, bn1a_g, bn1a_b, C1, tot1_8);
    pw_kernel<C1><<<dim3(HW/128, 2, NB), 256>>>(p_dwex, p_dwq, p_cat,
                                                pw1_w, bn1b_g, bn1b_b, 2*C1);

    int tot2_8 = NB*2*C1*HW/8;
    dw8_kernel<<<dim3(tot2_8/256, 1), 256>>>(p_cat, p_cat, p_dwf, p_dwf,
                                             dwf_w, bnfa_g, bnfa_b, 2*C1, tot2_8);
    pw_kernel<2*C1><<<dim3(HW/128, 1, NB), 256>>>(p_dwf, p_dwf, (float*)d_out,
                                                  pwf_w, bnfb_g, bnfb_b, C1);
}

// round 17
// speedup vs baseline: 1.0236x; 1.0236x over previous
#include <cuda_runtime.h>
#include <math.h>

#define NB 8
#define C1 128
#define HH 128
#define WW 128
#define HW (HH*WW)
#define KK 7
#define SS 4
#define DD 49
#define D8 56
#define NPH 31
#define PP 19
#define NPATCH (PP*PP)
#define NT 448
#define WTS 132
#define EXQ 7296

__device__ __forceinline__ int crow(int c) { return c*D8 + (c & ~3); }

// ---------------- scratch (static device globals) ----------------
__device__ float g_exsum[NB*C1*HW];
__device__ float g_qsum [NB*C1*HW];
__device__ float g_dwex [NB*C1*HW];
__device__ float g_dwq  [NB*C1*HW];
__device__ float g_cat  [NB*2*C1*HW];
__device__ float g_dwf  [NB*2*C1*HW];

#define S_EX    0
#define S_Q     (EXQ)
#define S_COR   (2*EXQ)
#define S_B     (3*EXQ)
#define S_A1    (S_B  + D8*D8)
#define S_CMAX  (S_A1 + D8*D8)
#define S_CRS   (S_CMAX + D8)
#define S_RMAX  (S_CRS  + D8)
#define S_RRS   (S_RMAX + D8)
#define S_ME    (S_RRS  + D8)
#define S_MQ    (S_ME   + D8)
#define S_G1    (S_MQ   + D8)
#define S_G2    (S_G1   + C1)
#define S_TOT   (S_G2   + C1)
#define SMEM_BYTES (S_TOT * 4)       // 115,008 B -> 2 CTAs/SM

__device__ __forceinline__ int pmap(int t) { return (t / 7) * 8 + (t % 7); }

// =====================================================================
__global__ __launch_bounds__(NT, 2) void attn_kernel(
    const float* __restrict__ ex, const float* __restrict__ q,
    const float* __restrict__ wce, const float* __restrict__ g1,
    const float* __restrict__ g2)
{
    extern __shared__ float sm[];
    float* s_ex  = sm + S_EX;
    float* s_q   = sm + S_Q;
    float* s_cor = sm + S_COR;
    float* s_b   = sm + S_B;
    float* s_a1  = sm + S_A1;
    float* s_wt  = sm + S_B;
    float* s_cmax= sm + S_CMAX;
    float* s_crs = sm + S_CRS;
    float* s_rmax= sm + S_RMAX;
    float* s_rrs = sm + S_RRS;
    float* s_me  = sm + S_ME;
    float* s_mq  = sm + S_MQ;
    float* s_g1  = sm + S_G1;
    float* s_g2  = sm + S_G2;

    const int tid  = threadIdx.x;
    const int lane = tid & 31;
    const int wid  = tid >> 5;
    const int n    = blockIdx.x / NPATCH;
    const int pv   = blockIdx.x % NPATCH;
    const int phv  = pv / PP, pwv = pv % PP;
    const int b    = phv * NPH + pwv;

    const bool act  = tid < 224;
    const int  c0w  = (tid / 14) * 8;
    const int  t14  = (tid % 14) * 4;
    const int  cb0  = crow(c0w);
    const int  cb1  = cb0 + 4*D8 + 4;

    if (tid < C1) { s_g1[tid] = g1[tid]; s_g2[tid] = g2[tid]; }

    // ---- vectorized patch load, coalesced mapping ----
    const float* exn = ex + (size_t)n*C1*HW;
    const float* qn  = q  + (size_t)n*C1*HW;
    #pragma unroll
    for (int it = 0; it < 2; it++) {
        int task = tid + it*NT;
        if (task < C1*KK) {
            int kh = task / C1, cp = task % C1;
            int m  = b*C1 + cp;
            int c  = m / 961;
            int p  = m % 961;
            int pht = p / NPH, pwt = p % NPH;
            int base = c*HW + (pht*SS + kh)*WW + pwt*SS;
            int r = crow(cp) + kh*8;
            float4 v0 = *(const float4*)(exn + base);
            float4 v1 = *(const float4*)(exn + base + 4);
            v1.w = 0.f;
            *(float4*)&s_ex[r]     = v0;
            *(float4*)&s_ex[r + 4] = v1;
            float4 u0 = *(const float4*)(qn + base);
            float4 u1 = *(const float4*)(qn + base + 4);
            u1.w = 0.f;
            *(float4*)&s_q[r]     = u0;
            *(float4*)&s_q[r + 4] = u1;
        }
    }

    // ---- stage 1: corr[c][d] = sum_k w[c][k]*ex[k][d]; 8c x 4d tiles ----
    {
        float acc[8][4] = {};
        for (int ch = 0; ch < 4; ch++) {
            __syncthreads();
            for (int t2 = tid; t2 < 1024; t2 += NT) {
                int c = t2 >> 3, kq = (t2 & 7) * 4;
                float4 wv = __ldg((const float4*)(wce + (size_t)c*C1 + ch*32 + kq));
                s_wt[(kq+0)*WTS + c] = wv.x;
                s_wt[(kq+1)*WTS + c] = wv.y;
                s_wt[(kq+2)*WTS + c] = wv.z;
                s_wt[(kq+3)*WTS + c] = wv.w;
            }
            __syncthreads();
            if (act) {
                #pragma unroll 2
                for (int k4 = 0; k4 < 32; k4 += 4) {
                    int kb = crow(ch*32 + k4);
                    #pragma unroll
                    for (int j = 0; j < 4; j++) {
                        float4 ev = *(const float4*)&s_ex[kb + j*D8 + t14];
                        float4 wl = *(const float4*)&s_wt[(k4+j)*WTS + c0w];
                        float4 wh = *(const float4*)&s_wt[(k4+j)*WTS + c0w + 4];
                        acc[0][0]+=wl.x*ev.x; acc[0][1]+=wl.x*ev.y; acc[0][2]+=wl.x*ev.z; acc[0][3]+=wl.x*ev.w;
                        acc[1][0]+=wl.y*ev.x; acc[1][1]+=wl.y*ev.y; acc[1][2]+=wl.y*ev.z; acc[1][3]+=wl.y*ev.w;
                        acc[2][0]+=wl.z*ev.x; acc[2][1]+=wl.z*ev.y; acc[2][2]+=wl.z*ev.z; acc[2][3]+=wl.z*ev.w;
                        acc[3][0]+=wl.w*ev.x; acc[3][1]+=wl.w*ev.y; acc[3][2]+=wl.w*ev.z; acc[3][3]+=wl.w*ev.w;
                        acc[4][0]+=wh.x*ev.x; acc[4][1]+=wh.x*ev.y; acc[4][2]+=wh.x*ev.z; acc[4][3]+=wh.x*ev.w;
                        acc[5][0]+=wh.y*ev.x; acc[5][1]+=wh.y*ev.y; acc[5][2]+=wh.y*ev.z; acc[5][3]+=wh.y*ev.w;
                        acc[6][0]+=wh.z*ev.x; acc[6][1]+=wh.z*ev.y; acc[6][2]+=wh.z*ev.z; acc[6][3]+=wh.z*ev.w;
                        acc[7][0]+=wh.w*ev.x; acc[7][1]+=wh.w*ev.y; acc[7][2]+=wh.w*ev.z; acc[7][3]+=wh.w*ev.w;
                    }
                }
            }
        }
        __syncthreads();
        if (act) {
            #pragma unroll
            for (int i = 0; i < 4; i++) {
                *(float4*)&s_cor[cb0 + i*D8 + t14] = make_float4(acc[i  ][0],acc[i  ][1],acc[i  ][2],acc[i  ][3]);
                *(float4*)&s_cor[cb1 + i*D8 + t14] = make_float4(acc[i+4][0],acc[i+4][1],acc[i+4][2],acc[i+4][3]);
            }
        }
    }
    __syncthreads();

    // ---- stage 2: A[d][e] = sum_c corr[c][d]*q[c][e]; 8d x 4e, split-K x2 ----
    if (tid < 196) {
        const int th = tid % 98;
        const int ks = tid / 98;
        const int d0 = (th / 14) * 8;
        const int e0 = (th % 14) * 4;
        const int k0 = ks * 64;
        float acc[8][4] = {};
        for (int c4 = k0; c4 < k0 + 64; c4 += 4) {
            int cr = crow(c4);
            #pragma unroll
            for (int j = 0; j < 4; j++) {
                const float* rp = &s_cor[cr + j*D8];
                float4 cl = *(const float4*)(rp + d0);
                float4 ch = *(const float4*)(rp + d0 + 4);
                float4 qe = *(const float4*)&s_q[cr + j*D8 + e0];
                acc[0][0]+=cl.x*qe.x; acc[0][1]+=cl.x*qe.y; acc[0][2]+=cl.x*qe.z; acc[0][3]+=cl.x*qe.w;
                acc[1][0]+=cl.y*qe.x; acc[1][1]+=cl.y*qe.y; acc[1][2]+=cl.y*qe.z; acc[1][3]+=cl.y*qe.w;
                acc[2][0]+=cl.z*qe.x; acc[2][1]+=cl.z*qe.y; acc[2][2]+=cl.z*qe.z; acc[2][3]+=cl.z*qe.w;
                acc[3][0]+=cl.w*qe.x; acc[3][1]+=cl.w*qe.y; acc[3][2]+=cl.w*qe.z; acc[3][3]+=cl.w*qe.w;
                acc[4][0]+=ch.x*qe.x; acc[4][1]+=ch.x*qe.y; acc[4][2]+=ch.x*qe.z; acc[4][3]+=ch.x*qe.w;
                acc[5][0]+=ch.y*qe.x; acc[5][1]+=ch.y*qe.y; acc[5][2]+=ch.y*qe.z; acc[5][3]+=ch.y*qe.w;
                acc[6][0]+=ch.z*qe.x; acc[6][1]+=ch.z*qe.y; acc[6][2]+=ch.z*qe.z; acc[6][3]+=ch.z*qe.w;
                acc[7][0]+=ch.w*qe.x; acc[7][1]+=ch.w*qe.y; acc[7][2]+=ch.w*qe.z; acc[7][3]+=ch.w*qe.w;
            }
        }
        float* dst = ks ? s_a1 : s_b;
        #pragma unroll
        for (int i = 0; i < 8; i++)
            *(float4*)&dst[(d0+i)*D8 + e0] = make_float4(acc[i][0],acc[i][1],acc[i][2],acc[i][3]);
    }
    __syncthreads();

    // ---- col-softmax stats ----
    {
        float* spm = s_cor;
        float* sps = s_cor + 896;
        float m0=-1e30f, s0=0.f, m1=-1e30f, s1=0.f;
        const int c0p = pmap(lane);
        const int c1p = (lane < 17) ? pmap(lane + 32) : 0;
        for (int dt = wid; dt < DD; dt += 14) {
            int dp = pmap(dt);
            float v = s_b[dp*D8 + c0p] + s_a1[dp*D8 + c0p];
            if (v > m0) { s0 = s0*__expf(m0 - v) + 1.f; m0 = v; } else s0 += __expf(v - m0);
            if (lane < 17) {
                float u = s_b[dp*D8 + c1p] + s_a1[dp*D8 + c1p];
                if (u > m1) { s1 = s1*__expf(m1 - u) + 1.f; m1 = u; } else s1 += __expf(u - m1);
            }
        }
        spm[wid*52 + lane] = m0;
        sps[wid*52 + lane] = s0;
        if (lane < 17) { spm[wid*52 + 32 + lane] = m1; sps[wid*52 + 32 + lane] = s1; }
    }
    // ---- row-softmax stats ----
    for (int task = wid; task < DD; task += 14) {
        int dp = pmap(task);
        int ep0 = pmap(lane);
        float v0 = s_b[dp*D8 + ep0] + s_a1[dp*D8 + ep0];
        float v1 = -1e30f;
        if (lane < 17) { int ep1 = pmap(lane + 32); v1 = s_b[dp*D8 + ep1] + s_a1[dp*D8 + ep1]; }
        float m = fmaxf(v0, v1);
        #pragma unroll
        for (int o = 16; o; o >>= 1) m = fmaxf(m, __shfl_xor_sync(~0u, m, o));
        float s = __expf(v0 - m) + ((lane < 17) ? __expf(v1 - m) : 0.f);
        #pragma unroll
        for (int o = 16; o; o >>= 1) s += __shfl_xor_sync(~0u, s, o);
        if (lane == 0) { s_rmax[dp] = m; s_rrs[dp] = 1.f / s; }
    }
    __syncthreads();
    if (tid < DD) {
        float* spm = s_cor;
        float* sps = s_cor + 896;
        float m = -1e30f;
        #pragma unroll
        for (int w2 = 0; w2 < 14; w2++) m = fmaxf(m, spm[w2*52 + tid]);
        float s = 0.f;
        #pragma unroll
        for (int w2 = 0; w2 < 14; w2++) s += sps[w2*52 + tid] * __expf(spm[w2*52 + tid] - m);
        s_cmax[pmap(tid)] = m;
        s_crs [pmap(tid)] = 1.f / s;
    }
    __syncthreads();

    // ---- softmax exp pass ----
    for (int i = tid; i < D8*D8; i += NT) {
        int dp = i / D8, ep = i % D8;
        bool pad = ((dp & 7) == 7) || ((ep & 7) == 7);
        float a = s_b[i] + s_a1[i];
        float a1v = pad ? 0.f : __expf(a - s_cmax[ep]) * s_crs[ep];
        float b2v = pad ? 0.f : __expf(a - s_rmax[dp]) * s_rrs[dp];
        s_a1[i] = a1v;
        s_b [i] = b2v;
    }
    __syncthreads();

    // ---- stage 3a: query_att[c][e] = sum_d ex[c][d]*A1[d][e]; 8c x 4e ----
    {
        float acc[8][4] = {};
        if (act) {
            for (int d4 = 0; d4 < D8; d4 += 4) {
                float4 a0v = *(const float4*)&s_a1[(d4+0)*D8 + t14];
                float4 a1v = *(const float4*)&s_a1[(d4+1)*D8 + t14];
                float4 a2v = *(const float4*)&s_a1[(d4+2)*D8 + t14];
                float4 a3v = *(const float4*)&s_a1[(d4+3)*D8 + t14];
                #pragma unroll
                for (int h = 0; h < 2; h++) {
                    int cb = h ? cb1 : cb0;
                    int o  = h * 4;
                    float4 x0 = *(const float4*)&s_ex[cb + 0*D8 + d4];
                    float4 x1 = *(const float4*)&s_ex[cb + 1*D8 + d4];
                    float4 x2 = *(const float4*)&s_ex[cb + 2*D8 + d4];
                    float4 x3 = *(const float4*)&s_ex[cb + 3*D8 + d4];
                    acc[o+0][0]+=x0.x*a0v.x+x0.y*a1v.x+x0.z*a2v.x+x0.w*a3v.x;
                    acc[o+0][1]+=x0.x*a0v.y+x0.y*a1v.y+x0.z*a2v.y+x0.w*a3v.y;
                    acc[o+0][2]+=x0.x*a0v.z+x0.y*a1v.z+x0.z*a2v.z+x0.w*a3v.z;
                    acc[o+0][3]+=x0.x*a0v.w+x0.y*a1v.w+x0.z*a2v.w+x0.w*a3v.w;
                    acc[o+1][0]+=x1.x*a0v.x+x1.y*a1v.x+x1.z*a2v.x+x1.w*a3v.x;
                    acc[o+1][1]+=x1.x*a0v.y+x1.y*a1v.y+x1.z*a2v.y+x1.w*a3v.y;
                    acc[o+1][2]+=x1.x*a0v.z+x1.y*a1v.z+x1.z*a2v.z+x1.w*a3v.z;
                    acc[o+1][3]+=x1.x*a0v.w+x1.y*a1v.w+x1.z*a2v.w+x1.w*a3v.w;
                    acc[o+2][0]+=x2.x*a0v.x+x2.y*a1v.x+x2.z*a2v.x+x2.w*a3v.x;
                    acc[o+2][1]+=x2.x*a0v.y+x2.y*a1v.y+x2.z*a2v.y+x2.w*a3v.y;
                    acc[o+2][2]+=x2.x*a0v.z+x2.y*a1v.z+x2.z*a2v.z+x2.w*a3v.z;
                    acc[o+2][3]+=x2.x*a0v.w+x2.y*a1v.w+x2.z*a2v.w+x2.w*a3v.w;
                    acc[o+3][0]+=x3.x*a0v.x+x3.y*a1v.x+x3.z*a2v.x+x3.w*a3v.x;
                    acc[o+3][1]+=x3.x*a0v.y+x3.y*a1v.y+x3.z*a2v.y+x3.w*a3v.y;
                    acc[o+3][2]+=x3.x*a0v.z+x3.y*a1v.z+x3.z*a2v.z+x3.w*a3v.z;
                    acc[o+3][3]+=x3.x*a0v.w+x3.y*a1v.w+x3.z*a2v.w+x3.w*a3v.w;
                }
            }
        }
        __syncthreads();
        if (act) {
            #pragma unroll
            for (int i = 0; i < 4; i++) {
                *(float4*)&s_cor[cb0 + i*D8 + t14] = make_float4(acc[i  ][0],acc[i  ][1],acc[i  ][2],acc[i  ][3]);
                *(float4*)&s_cor[cb1 + i*D8 + t14] = make_float4(acc[i+4][0],acc[i+4][1],acc[i+4][2],acc[i+4][3]);
            }
        }
    }
    __syncthreads();

    // ---- stage 3b: exemplar_att[c][d] = sum_e q[c][e]*B2[d][e]; 8c x 4d ----
    {
        float acc[8][4] = {};
        if (act) {
            for (int e4 = 0; e4 < D8; e4 += 4) {
                float4 b0 = *(const float4*)&s_b[(t14+0)*D8 + e4];
                float4 b1 = *(const float4*)&s_b[(t14+1)*D8 + e4];
                float4 b2 = *(const float4*)&s_b[(t14+2)*D8 + e4];
                float4 b3 = *(const float4*)&s_b[(t14+3)*D8 + e4];
                #pragma unroll
                for (int h = 0; h < 2; h++) {
                    int cb = h ? cb1 : cb0;
                    int o  = h * 4;
                    float4 q0 = *(const float4*)&s_q[cb + 0*D8 + e4];
                    float4 q1 = *(const float4*)&s_q[cb + 1*D8 + e4];
                    float4 q2 = *(const float4*)&s_q[cb + 2*D8 + e4];
                    float4 q3 = *(const float4*)&s_q[cb + 3*D8 + e4];
                    acc[o+0][0]+=q0.x*b0.x+q0.y*b0.y+q0.z*b0.z+q0.w*b0.w;
                    acc[o+0][1]+=q0.x*b1.x+q0.y*b1.y+q0.z*b1.z+q0.w*b1.w;
                    acc[o+0][2]+=q0.x*b2.x+q0.y*b2.y+q0.z*b2.z+q0.w*b2.w;
                    acc[o+0][3]+=q0.x*b3.x+q0.y*b3.y+q0.z*b3.z+q0.w*b3.w;
                    acc[o+1][0]+=q1.x*b0.x+q1.y*b0.y+q1.z*b0.z+q1.w*b0.w;
                    acc[o+1][1]+=q1.x*b1.x+q1.y*b1.y+q1.z*b1.z+q1.w*b1.w;
                    acc[o+1][2]+=q1.x*b2.x+q1.y*b2.y+q1.z*b2.z+q1.w*b2.w;
                    acc[o+1][3]+=q1.x*b3.x+q1.y*b3.y+q1.z*b3.z+q1.w*b3.w;
                    acc[o+2][0]+=q2.x*b0.x+q2.y*b0.y+q2.z*b0.z+q2.w*b0.w;
                    acc[o+2][1]+=q2.x*b1.x+q2.y*b1.y+q2.z*b1.z+q2.w*b1.w;
                    acc[o+2][2]+=q2.x*b2.x+q2.y*b2.y+q2.z*b2.z+q2.w*b2.w;
                    acc[o+2][3]+=q2.x*b3.x+q2.y*b3.y+q2.z*b3.z+q2.w*b3.w;
                    acc[o+3][0]+=q3.x*b0.x+q3.y*b0.y+q3.z*b0.z+q3.w*b0.w;
                    acc[o+3][1]+=q3.x*b1.x+q3.y*b1.y+q3.z*b1.z+q3.w*b1.w;
                    acc[o+3][2]+=q3.x*b2.x+q3.y*b2.y+q3.z*b2.z+q3.w*b2.w;
                    acc[o+3][3]+=q3.x*b3.x+q3.y*b3.y+q3.z*b3.z+q3.w*b3.w;
                }
            }
        }
        __syncthreads();
        if (act) {
            #pragma unroll
            for (int i = 0; i < 4; i++) {
                *(float4*)&s_ex[cb0 + i*D8 + t14] = make_float4(acc[i  ][0],acc[i  ][1],acc[i  ][2],acc[i  ][3]);
                *(float4*)&s_ex[cb1 + i*D8 + t14] = make_float4(acc[i+4][0],acc[i+4][1],acc[i+4][2],acc[i+4][3]);
            }
        }
    }
    __syncthreads();

    // ---- gates ----
    {
        float* sp1 = s_a1;
        float* sp2 = s_a1 + 896;
        float p0 = 0.f, p1 = 0.f, r0 = 0.f, r1 = 0.f;
        for (int c = wid; c < C1; c += 14) {
            int cr = crow(c);
            float gA = s_g1[c], gB = s_g2[c];
            p0 += gA * s_ex [cr + lane];
            r0 += gB * s_cor[cr + lane];
            if (lane < 24) {
                p1 += gA * s_ex [cr + 32 + lane];
                r1 += gB * s_cor[cr + 32 + lane];
            }
        }
        sp1[wid*64 + lane] = p0;
        sp2[wid*64 + lane] = r0;
        if (lane < 24) { sp1[wid*64 + 32 + lane] = p1; sp2[wid*64 + 32 + lane] = r1; }
    }
    __syncthreads();
    if (tid < D8) {
        float* sp1 = s_a1;
        float* sp2 = s_a1 + 896;
        float sa = 0.f, sb2 = 0.f;
        #pragma unroll
        for (int w2 = 0; w2 < 14; w2++) { sa += sp1[w2*64 + tid]; sb2 += sp2[w2*64 + tid]; }
        s_me[tid] = 1.f / (1.f + __expf(-sa));
        s_mq[tid] = 1.f / (1.f + __expf(-sb2));
    }
    __syncthreads();

    // ---- recon + residual ----
    for (int i = tid; i < C1*DD; i += NT) {
        int c = i / DD, d = i % DD;
        int kh = d / KK, kw = d % KK;
        int dp = kh*8 + kw;
        int cr = crow(c);
        int y = phv*KK + kh, x = pwv*KK + kw;
        if (y < HH && x < WW) {
            size_t gi = (size_t)(n*C1 + c)*HW + y*WW + x;
            g_exsum[gi] = s_ex [cr + dp]*s_me[dp] + ex[gi];
            g_qsum [gi] = s_cor[cr + dp]*s_mq[dp] + q [gi];
        }
    }
}

// =====================================================================
// Depthwise 3x3 (pad 1) + BN + ReLU — 1 thread = 4 pixels, dual-stream.
// =====================================================================
__global__ __launch_bounds__(256) void dw4_kernel(
    const float* __restrict__ in0, const float* __restrict__ in1,
    float* __restrict__ out0, float* __restrict__ out1,
    const float* __restrict__ w, const float* __restrict__ g,
    const float* __restrict__ b, int Ctot, int total4)
{
    int idx = blockIdx.x*blockDim.x + threadIdx.x;
    if (idx >= total4) return;
    const float* in  = blockIdx.y ? in1  : in0;
    float*       out = blockIdx.y ? out1 : out0;
    const int W4 = WW / 4;
    int x4    = (idx % W4) * 4;
    int y     = (idx / W4) % HH;
    int plane = idx / (W4 * HH);
    int c     = plane % Ctot;
    const float* ip = in + (size_t)plane*HW;

    const float* wc = w + c*9;
    float w00=wc[0], w01=wc[1], w02=wc[2];
    float w10=wc[3], w11=wc[4], w12=wc[5];
    float w20=wc[6], w21=wc[7], w22=wc[8];

    float acc0=0.f, acc1=0.f, acc2=0.f, acc3=0.f;

    #pragma unroll
    for (int dy = -1; dy <= 1; dy++) {
        int yy = y + dy;
        if (yy < 0 || yy >= HH) continue;
        const float* row = ip + yy*WW;
        float4 M = *(const float4*)(row + x4);
        float lm = (x4 > 0)        ? row[x4 - 1] : 0.f;
        float rp = (x4 + 4 < WW)   ? row[x4 + 4] : 0.f;
        float wa = (dy < 0) ? w00 : (dy ? w20 : w10);
        float wb = (dy < 0) ? w01 : (dy ? w21 : w11);
        float wd = (dy < 0) ? w02 : (dy ? w22 : w12);
        acc0 += wa*lm  + wb*M.x + wd*M.y;
        acc1 += wa*M.x + wb*M.y + wd*M.z;
        acc2 += wa*M.y + wb*M.z + wd*M.w;
        acc3 += wa*M.z + wb*M.w + wd*rp;
    }

    float gs = g[c] * rsqrtf(1.f + 1e-5f);
    float bb = b[c];
    float4 o;
    o.x = fmaxf(acc0*gs + bb, 0.f);
    o.y = fmaxf(acc1*gs + bb, 0.f);
    o.z = fmaxf(acc2*gs + bb, 0.f);
    o.w = fmaxf(acc3*gs + bb, 0.f);
    *(float4*)(out + (size_t)plane*HW + y*WW + x4) = o;
}

// =====================================================================
// Pointwise 1x1 conv as SGEMM (R15-proven: k-chunk 8, double-buffered).
// =====================================================================
template<int CIN>
__global__ __launch_bounds__(256) void pw_kernel(
    const float* __restrict__ in0, const float* __restrict__ in1,
    float* __restrict__ out,
    const float* __restrict__ w, const float* __restrict__ gsc,
    const float* __restrict__ bsc, int ostride)
{
    __shared__ float As[2][8][128];
    __shared__ float Bs[2][8][128];
    const int n   = blockIdx.z;
    const int px0 = blockIdx.x * 128;
    const int co_off = blockIdx.y * C1;
    const float* in = blockIdx.y ? in1 : in0;
    const int t   = threadIdx.x;
    const int tx  = t % 16, ty = t / 16;
    const int ci  = t % 128, k4 = (t / 128) * 4;
    const int kr  = t / 32,  pc = (t % 32) * 4;

    float acc[8][8] = {};
    const float* inb = in + (size_t)n*CIN*HW + px0;

    float4 wv = __ldg((const float4*)(w + (size_t)ci*CIN + k4));
    float4 bv = __ldg((const float4*)(inb + (size_t)kr*HW + pc));

    for (int kt = 0; kt < CIN; kt += 8) {
        int buf = (kt >> 3) & 1;
        As[buf][k4+0][ci] = wv.x; As[buf][k4+1][ci] = wv.y;
        As[buf][k4+2][ci] = wv.z; As[buf][k4+3][ci] = wv.w;
        *(float4*)&Bs[buf][kr][pc] = bv;
        __syncthreads();
        if (kt + 8 < CIN) {
            wv = __ldg((const float4*)(w + (size_t)ci*CIN + kt + 8 + k4));
            bv = __ldg((const float4*)(inb + (size_t)(kt + 8 + kr)*HW + pc));
        }
        #pragma unroll
        for (int k = 0; k < 8; k++) {
            float4 a0 = *(float4*)&As[buf][k][ty*4];
            float4 a1 = *(float4*)&As[buf][k][64 + ty*4];
            float4 b0 = *(float4*)&Bs[buf][k][tx*4];
            float4 b1 = *(float4*)&Bs[buf][k][64 + tx*4];
            acc[0][0]+=a0.x*b0.x; acc[0][1]+=a0.x*b0.y; acc[0][2]+=a0.x*b0.z; acc[0][3]+=a0.x*b0.w;
            acc[0][4]+=a0.x*b1.x; acc[0][5]+=a0.x*b1.y; acc[0][6]+=a0.x*b1.z; acc[0][7]+=a0.x*b1.w;
            acc[1][0]+=a0.y*b0.x; acc[1][1]+=a0.y*b0.y; acc[1][2]+=a0.y*b0.z; acc[1][3]+=a0.y*b0.w;
            acc[1][4]+=a0.y*b1.x; acc[1][5]+=a0.y*b1.y; acc[1][6]+=a0.y*b1.z; acc[1][7]+=a0.y*b1.w;
            acc[2][0]+=a0.z*b0.x; acc[2][1]+=a0.z*b0.y; acc[2][2]+=a0.z*b0.z; acc[2][3]+=a0.z*b0.w;
            acc[2][4]+=a0.z*b1.x; acc[2][5]+=a0.z*b1.y; acc[2][6]+=a0.z*b1.z; acc[2][7]+=a0.z*b1.w;
            acc[3][0]+=a0.w*b0.x; acc[3][1]+=a0.w*b0.y; acc[3][2]+=a0.w*b0.z; acc[3][3]+=a0.w*b0.w;
            acc[3][4]+=a0.w*b1.x; acc[3][5]+=a0.w*b1.y; acc[3][6]+=a0.w*b1.z; acc[3][7]+=a0.w*b1.w;
            acc[4][0]+=a1.x*b0.x; acc[4][1]+=a1.x*b0.y; acc[4][2]+=a1.x*b0.z; acc[4][3]+=a1.x*b0.w;
            acc[4][4]+=a1.x*b1.x; acc[4][5]+=a1.x*b1.y; acc[4][6]+=a1.x*b1.z; acc[4][7]+=a1.x*b1.w;
            acc[5][0]+=a1.y*b0.x; acc[5][1]+=a1.y*b0.y; acc[5][2]+=a1.y*b0.z; acc[5][3]+=a1.y*b0.w;
            acc[5][4]+=a1.y*b1.x; acc[5][5]+=a1.y*b1.y; acc[5][6]+=a1.y*b1.z; acc[5][7]+=a1.y*b1.w;
            acc[6][0]+=a1.z*b0.x; acc[6][1]+=a1.z*b0.y; acc[6][2]+=a1.z*b0.z; acc[6][3]+=a1.z*b0.w;
            acc[6][4]+=a1.z*b1.x; acc[6][5]+=a1.z*b1.y; acc[6][6]+=a1.z*b1.z; acc[6][7]+=a1.z*b1.w;
            acc[7][0]+=a1.w*b0.x; acc[7][1]+=a1.w*b0.y; acc[7][2]+=a1.w*b0.z; acc[7][3]+=a1.w*b0.w;
            acc[7][4]+=a1.w*b1.x; acc[7][5]+=a1.w*b1.y; acc[7][6]+=a1.w*b1.z; acc[7][7]+=a1.w*b1.w;
        }
        __syncthreads();
    }

    #pragma unroll
    for (int i = 0; i < 8; i++) {
        int co = (i < 4) ? (ty*4 + i) : (64 + ty*4 + (i - 4));
        float gv = gsc[co] * rsqrtf(1.f + 1e-5f);
        float bb = bsc[co];
        float* ob = out + ((size_t)n*ostride + co_off + co)*HW + px0;
        float4 o0, o1;
        o0.x = fmaxf(acc[i][0]*gv + bb, 0.f);
        o0.y = fmaxf(acc[i][1]*gv + bb, 0.f);
        o0.z = fmaxf(acc[i][2]*gv + bb, 0.f);
        o0.w = fmaxf(acc[i][3]*gv + bb, 0.f);
        o1.x = fmaxf(acc[i][4]*gv + bb, 0.f);
        o1.y = fmaxf(acc[i][5]*gv + bb, 0.f);
        o1.z = fmaxf(acc[i][6]*gv + bb, 0.f);
        o1.w = fmaxf(acc[i][7]*gv + bb, 0.f);
        *(float4*)(ob + tx*4)      = o0;
        *(float4*)(ob + 64 + tx*4) = o1;
    }
}

// =====================================================================
extern "C" void kernel_launch(void* const* d_in, const int* in_sizes, int n_in,
                              void* d_out, int out_size)
{
    const float* exemplar = (const float*)d_in[0];
    const float* query    = (const float*)d_in[1];
    const float* w_conv_e = (const float*)d_in[2];
    const float* w_gate1  = (const float*)d_in[3];
    const float* w_gate2  = (const float*)d_in[4];
    const float* dw1_w    = (const float*)d_in[5];
    const float* bn1a_g   = (const float*)d_in[6];
    const float* bn1a_b   = (const float*)d_in[7];
    const float* pw1_w    = (const float*)d_in[8];
    const float* bn1b_g   = (const float*)d_in[9];
    const float* bn1b_b   = (const float*)d_in[10];
    const float* dwf_w    = (const float*)d_in[11];
    const float* bnfa_g   = (const float*)d_in[12];
    const float* bnfa_b   = (const float*)d_in[13];
    const float* pwf_w    = (const float*)d_in[14];
    const float* bnfb_g   = (const float*)d_in[15];
    const float* bnfb_b   = (const float*)d_in[16];

    float *p_exsum, *p_qsum, *p_dwex, *p_dwq, *p_cat, *p_dwf;
    cudaGetSymbolAddress((void**)&p_exsum, g_exsum);
    cudaGetSymbolAddress((void**)&p_qsum,  g_qsum);
    cudaGetSymbolAddress((void**)&p_dwex,  g_dwex);
    cudaGetSymbolAddress((void**)&p_dwq,   g_dwq);
    cudaGetSymbolAddress((void**)&p_cat,   g_cat);
    cudaGetSymbolAddress((void**)&p_dwf,   g_dwf);

    cudaFuncSetAttribute(attn_kernel, cudaFuncAttributeMaxDynamicSharedMemorySize, SMEM_BYTES);

    attn_kernel<<<NB*NPATCH, NT, SMEM_BYTES>>>(exemplar, query, w_conv_e, w_gate1, w_gate2);

    int tot1_4 = NB*C1*HW/4;
    dw4_kernel<<<dim3(tot1_4/256, 2), 256>>>(p_exsum, p_qsum, p_dwex, p_dwq,
                                             dw1_w, bn1a_g, bn1a_b, C1, tot1_4);
    pw_kernel<C1><<<dim3(HW/128, 2, NB), 256>>>(p_dwex, p_dwq, p_cat,
                                                pw1_w, bn1b_g, bn1b_b, 2*C1);

    int tot2_4 = NB*2*C1*HW/4;
    dw4_kernel<<<dim3(tot2_4/256, 1), 256>>>(p_cat, p_cat, p_dwf, p_dwf,
                                             dwf_w, bnfa_g, bnfa_b, 2*C1, tot2_4);
    pw_kernel<2*C1><<<dim3(HW/128, 1, NB), 256>>>(p_dwf, p_dwf, (float*)d_out,
                                                  pwf_w, bnfb_g, bnfb_b, C1);
}